// round 1
// baseline (speedup 1.0000x reference)
#include <cuda_runtime.h>
#include <cuda_bf16.h>
#include <math.h>

#define HW     36864
#define IMG    192
#define CCH    192
#define HIDN   768
#define NWIN   144
#define NHEAD  6
#define NTOK   256
#define KINN   128
#define TOPKN  64

// ---------------- scratch buffers (static, no allocation) ----------------
__device__ __align__(128) float g_xn  [HW*CCH];
__device__ __align__(128) float g_q   [HW*CCH];
__device__ __align__(128) float g_k   [HW*CCH];
__device__ __align__(128) float g_v   [HW*CCH];
__device__ __align__(128) float g_vl  [HW*CCH];
__device__ __align__(128) float g_attn[HW*CCH];
__device__ __align__(128) float g_x2  [HW*CCH];
__device__ __align__(128) float g_yln [HW*CCH];
__device__ __align__(128) float g_yb  [HW*HIDN];
__device__ __align__(128) float g_y2  [HW*HIDN];

__device__ __forceinline__ float gelu_f(float x) {
    return 0.5f * x * (1.0f + erff(x * 0.70710678118654752f));
}

// ---------------- LN1: transpose (C,HW) -> (HW,C) + LayerNorm ----------------
__global__ void ln1_kernel(const float* __restrict__ f, const float* __restrict__ g,
                           const float* __restrict__ b, float* __restrict__ xn) {
    int p = blockIdx.x * 256 + threadIdx.x;
    float s = 0.f, s2 = 0.f;
    #pragma unroll 8
    for (int c = 0; c < CCH; c++) {
        float v = f[(size_t)c * HW + p];
        s += v; s2 += v * v;
    }
    float m = s * (1.0f / CCH);
    float var = s2 * (1.0f / CCH) - m * m;
    float r = rsqrtf(var + 1e-5f);
    #pragma unroll 8
    for (int c = 0; c < CCH; c++) {
        float v = f[(size_t)c * HW + p];
        xn[(size_t)p * CCH + c] = (v - m) * r * g[c] + b[c];
    }
}

// ---------------- LN2: row-major (HW,C) LayerNorm ----------------
__global__ void ln2_kernel(const float* __restrict__ x, const float* __restrict__ g,
                           const float* __restrict__ b, float* __restrict__ y) {
    int p = blockIdx.x * 256 + threadIdx.x;
    const float* row = x + (size_t)p * CCH;
    float s = 0.f, s2 = 0.f;
    #pragma unroll 8
    for (int c = 0; c < CCH; c++) { float v = row[c]; s += v; s2 += v * v; }
    float m = s * (1.0f / CCH);
    float var = s2 * (1.0f / CCH) - m * m;
    float r = rsqrtf(var + 1e-5f);
    float* orow = y + (size_t)p * CCH;
    #pragma unroll 8
    for (int c = 0; c < CCH; c++) orow[c] = (row[c] - m) * r * g[c] + b[c];
}

// ---------------- SGEMM: C[M,N] = A[M,K] @ B[K,N] + bias, opt act/residual ----
// BM=128, BN=64, BK=16, 128 threads, 8x8 per thread. All dims divide exactly.
// ACT: 0 none, 1 gelu. RES: 0 none, 1 += res[m*N+n], 2 += res[n*ldres+m]
template<int ACT, int RES>
__global__ void sgemm_kernel(const float* __restrict__ A, const float* __restrict__ B,
                             const float* __restrict__ bias, float* __restrict__ C,
                             int M, int N, int K,
                             const float* __restrict__ res, int ldres) {
    __shared__ float As[16][128];
    __shared__ float Bs[16][64];
    const int tid = threadIdx.x;
    const int m0 = blockIdx.y * 128, n0 = blockIdx.x * 64;
    const int tx = tid & 7, ty = tid >> 3;
    float acc[8][8];
    #pragma unroll
    for (int i = 0; i < 8; i++)
        #pragma unroll
        for (int j = 0; j < 8; j++) acc[i][j] = 0.f;

    for (int k0 = 0; k0 < K; k0 += 16) {
        #pragma unroll
        for (int it = 0; it < 4; it++) {
            int lin = tid + it * 128;            // 0..511
            int m = lin >> 2, k4 = lin & 3;
            float4 av = *(const float4*)(A + (size_t)(m0 + m) * K + k0 + k4 * 4);
            As[k4 * 4 + 0][m] = av.x; As[k4 * 4 + 1][m] = av.y;
            As[k4 * 4 + 2][m] = av.z; As[k4 * 4 + 3][m] = av.w;
        }
        #pragma unroll
        for (int it = 0; it < 2; it++) {
            int lin = tid + it * 128;            // 0..255
            int kk = lin >> 4, n4 = lin & 15;
            *(float4*)&Bs[kk][n4 * 4] =
                *(const float4*)(B + (size_t)(k0 + kk) * N + n0 + n4 * 4);
        }
        __syncthreads();
        #pragma unroll
        for (int kk = 0; kk < 16; kk++) {
            float a[8], bb[8];
            *(float4*)&a[0] = *(float4*)&As[kk][ty * 8];
            *(float4*)&a[4] = *(float4*)&As[kk][ty * 8 + 4];
            *(float4*)&bb[0] = *(float4*)&Bs[kk][tx * 8];
            *(float4*)&bb[4] = *(float4*)&Bs[kk][tx * 8 + 4];
            #pragma unroll
            for (int i = 0; i < 8; i++)
                #pragma unroll
                for (int j = 0; j < 8; j++) acc[i][j] += a[i] * bb[j];
        }
        __syncthreads();
    }
    const int mb = m0 + ty * 8, nb = n0 + tx * 8;
    #pragma unroll
    for (int i = 0; i < 8; i++) {
        #pragma unroll
        for (int j = 0; j < 8; j++) {
            float v = acc[i][j] + bias[nb + j];
            if (ACT == 1) v = gelu_f(v);
            if (RES == 1) v += res[(size_t)(mb + i) * N + nb + j];
            if (RES == 2) v += res[(size_t)(nb + j) * ldres + (mb + i)];
            C[(size_t)(mb + i) * N + nb + j] = v;
        }
    }
}

// ---------------- depthwise 5x5 conv (+bias) + exact GELU, opt input add ------
// in/out layout: (HW, Cn) row-major; conv over the 192x192 spatial grid.
__global__ void dwconv_kernel(const float* __restrict__ in, const float* __restrict__ wgt,
                              const float* __restrict__ bias, float* __restrict__ out,
                              int Cn, int addin) {
    int idx = blockIdx.x * 256 + threadIdx.x;
    int ch = idx % Cn;
    int p  = idx / Cn;
    int y = p / IMG, x = p % IMG;
    float acc = bias[ch];
    #pragma unroll
    for (int ky = 0; ky < 5; ky++) {
        int yy = y + ky - 2;
        if ((unsigned)yy >= (unsigned)IMG) continue;
        #pragma unroll
        for (int kx = 0; kx < 5; kx++) {
            int xx = x + kx - 2;
            if ((unsigned)xx >= (unsigned)IMG) continue;
            acc += in[(size_t)(yy * IMG + xx) * Cn + ch] * wgt[ch * 25 + ky * 5 + kx];
        }
    }
    float gg = gelu_f(acc);
    out[idx] = addin ? (in[idx] + gg) : gg;
}

// ---------------- attention: one CTA per (head, window), 256 threads ----------
// smem: ks[256*33] + vs[256*33] + sc[128*256] + js(uint8)[128*260] = 231936 B
#define ATTN_SMEM_BYTES 231936
__global__ void attn_kernel(const float* __restrict__ q, const float* __restrict__ k,
                            const float* __restrict__ v, const float* __restrict__ vl,
                            const float* __restrict__ pfa_v, const int* __restrict__ pfa_i,
                            const int* __restrict__ rpi, const float* __restrict__ rpb,
                            float* __restrict__ out) {
    extern __shared__ float sm[];
    float* ks = sm;                         // 256*33
    float* vs = ks + 256 * 33;              // 256*33
    float* sc = vs + 256 * 33;              // 128*256 : sc[kk*256 + t]
    unsigned char* js = (unsigned char*)(sc + 128 * 256);  // 128*260

    const int t = threadIdx.x;              // query index in window, 0..255
    const int h = blockIdx.x;               // head
    const int w = blockIdx.y;               // window
    const int wy = w / 12, wx = w % 12;
    const size_t whbase = ((size_t)w * NHEAD + h) * NTOK;

    // stage K and V rows for this (window, head)
    {
        int r = t;
        int pj = (wy * 16 + (r >> 4)) * IMG + wx * 16 + (r & 15);
        const float4* kr = (const float4*)(k + (size_t)pj * CCH + h * 32);
        const float4* vr = (const float4*)(v + (size_t)pj * CCH + h * 32);
        #pragma unroll
        for (int e = 0; e < 8; e++) {
            float4 a = kr[e];
            ks[r * 33 + e * 4 + 0] = a.x; ks[r * 33 + e * 4 + 1] = a.y;
            ks[r * 33 + e * 4 + 2] = a.z; ks[r * 33 + e * 4 + 3] = a.w;
            float4 bqv = vr[e];
            vs[r * 33 + e * 4 + 0] = bqv.x; vs[r * 33 + e * 4 + 1] = bqv.y;
            vs[r * 33 + e * 4 + 2] = bqv.z; vs[r * 33 + e * 4 + 3] = bqv.w;
        }
    }
    // stage gather indices (coalesced global read, transposed uint8 smem layout)
    {
        const int* idxg = pfa_i + whbase * KINN;
        for (int e = t; e < NTOK * KINN; e += 256) {
            int il = e >> 7, kk = e & 127;
            js[kk * 260 + il] = (unsigned char)idxg[e];
        }
    }
    __syncthreads();

    const int i = t;
    const int pi = (wy * 16 + (i >> 4)) * IMG + wx * 16 + (i & 15);

    // q row (scaled by hd^-0.5)
    float qreg[32];
    {
        const float4* qr = (const float4*)(q + (size_t)pi * CCH + h * 32);
        const float scl = 0.17677669529663688f;  // 1/sqrt(32)
        #pragma unroll
        for (int e = 0; e < 8; e++) {
            float4 a = qr[e];
            qreg[e * 4 + 0] = a.x * scl; qreg[e * 4 + 1] = a.y * scl;
            qreg[e * 4 + 2] = a.z * scl; qreg[e * 4 + 3] = a.w * scl;
        }
    }

    // gathered scores + rpb
    const int* rr = rpi + i * NTOK;
    float mx = -1e30f;
    #pragma unroll 2
    for (int kk = 0; kk < KINN; kk++) {
        int j = js[kk * 260 + t];
        const float* kj = ks + j * 33;
        float d = 0.f;
        #pragma unroll
        for (int dd = 0; dd < 32; dd++) d += qreg[dd] * kj[dd];
        d += __ldg(&rpb[__ldg(&rr[j]) * NHEAD + h]);
        sc[kk * 256 + t] = d;
        mx = fmaxf(mx, d);
    }

    // softmax over K=128
    float sE = 0.f;
    #pragma unroll 4
    for (int kk = 0; kk < KINN; kk++) {
        float e = __expf(sc[kk * 256 + t] - mx);
        sc[kk * 256 + t] = e;
        sE += e;
    }
    // multiply by pfa prior values
    const float* pv = pfa_v + (whbase + i) * KINN;
    float inv = 1.0f / sE;
    float sA = 0.f;
    #pragma unroll 4
    for (int kk = 0; kk < KINN; kk++) {
        float a = sc[kk * 256 + t] * pv[kk] * inv;
        sc[kk * 256 + t] = a;
        sA += a;
    }
    // renorm factor: final value = (a + EPS) * r2 — affine positive, monotonic,
    // so top-k selection order on raw 'a' matches the reference's on tv.
    const float r2 = 1.0f / (sA + 1e-10f);

    // top-64 repeated argmax (first-index-wins on ties, matching lax.top_k),
    // fused with sparse AV accumulation.
    float acc[32];
    #pragma unroll
    for (int dd = 0; dd < 32; dd++) acc[dd] = 0.f;
    for (int sel = 0; sel < TOPKN; sel++) {
        float best = -1.f; int bi = 0;
        #pragma unroll 8
        for (int kk = 0; kk < KINN; kk++) {
            float vv = sc[kk * 256 + t];
            if (vv > best) { best = vv; bi = kk; }
        }
        sc[bi * 256 + t] = -2.f;
        int j = js[bi * 260 + t];
        float aval = (best + 1e-10f) * r2;
        const float* vj = vs + j * 33;
        #pragma unroll
        for (int dd = 0; dd < 32; dd++) acc[dd] += aval * vj[dd];
    }

    // out = attn_out + v_LePE, written at the global pixel (implicit win-reverse)
    float* op = out + (size_t)pi * CCH + h * 32;
    const float* vp = vl + (size_t)pi * CCH + h * 32;
    #pragma unroll
    for (int e = 0; e < 8; e++) {
        float4 o;
        o.x = acc[e * 4 + 0] + vp[e * 4 + 0];
        o.y = acc[e * 4 + 1] + vp[e * 4 + 1];
        o.z = acc[e * 4 + 2] + vp[e * 4 + 2];
        o.w = acc[e * 4 + 3] + vp[e * 4 + 3];
        *(float4*)(op + e * 4) = o;
    }
}

// ---------------- launch ----------------
extern "C" void kernel_launch(void* const* d_in, const int* in_sizes, int n_in,
                              void* d_out, int out_size) {
    const float* features = (const float*)d_in[0];
    const float* pfa_v    = (const float*)d_in[1];
    const int*   pfa_i    = (const int*)  d_in[2];
    const int*   rpi      = (const int*)  d_in[3];
    const float* ln1_g    = (const float*)d_in[4];
    const float* ln1_b    = (const float*)d_in[5];
    const float* Wq_w     = (const float*)d_in[6];
    const float* Wq_b     = (const float*)d_in[7];
    const float* Wk_w     = (const float*)d_in[8];
    const float* Wk_b     = (const float*)d_in[9];
    const float* Wv_w     = (const float*)d_in[10];
    const float* Wv_b     = (const float*)d_in[11];
    const float* lepe_w   = (const float*)d_in[12];
    const float* lepe_b   = (const float*)d_in[13];
    const float* rpb_tab  = (const float*)d_in[14];
    const float* proj_w   = (const float*)d_in[15];
    const float* proj_b   = (const float*)d_in[16];
    const float* ln2_g    = (const float*)d_in[17];
    const float* ln2_b    = (const float*)d_in[18];
    const float* fc1_w    = (const float*)d_in[19];
    const float* fc1_b    = (const float*)d_in[20];
    const float* ffn_dw_w = (const float*)d_in[21];
    const float* ffn_dw_b = (const float*)d_in[22];
    const float* fc2_w    = (const float*)d_in[23];
    const float* fc2_b    = (const float*)d_in[24];
    float* outp = (float*)d_out;

    float *xn, *qb, *kb, *vb, *vlb, *attnb, *x2b, *ylnb, *ybb, *y2b;
    cudaGetSymbolAddress((void**)&xn,    g_xn);
    cudaGetSymbolAddress((void**)&qb,    g_q);
    cudaGetSymbolAddress((void**)&kb,    g_k);
    cudaGetSymbolAddress((void**)&vb,    g_v);
    cudaGetSymbolAddress((void**)&vlb,   g_vl);
    cudaGetSymbolAddress((void**)&attnb, g_attn);
    cudaGetSymbolAddress((void**)&x2b,   g_x2);
    cudaGetSymbolAddress((void**)&ylnb,  g_yln);
    cudaGetSymbolAddress((void**)&ybb,   g_yb);
    cudaGetSymbolAddress((void**)&y2b,   g_y2);

    cudaFuncSetAttribute(attn_kernel, cudaFuncAttributeMaxDynamicSharedMemorySize,
                         ATTN_SMEM_BYTES);

    const int M = HW;

    // 1) transpose + LN1
    ln1_kernel<<<HW / 256, 256>>>(features, ln1_g, ln1_b, xn);

    // 2) QKV projections
    dim3 g192(CCH / 64, M / 128);
    sgemm_kernel<0, 0><<<g192, 128>>>(xn, Wq_w, Wq_b, qb, M, CCH, CCH, nullptr, 0);
    sgemm_kernel<0, 0><<<g192, 128>>>(xn, Wk_w, Wk_b, kb, M, CCH, CCH, nullptr, 0);
    sgemm_kernel<0, 0><<<g192, 128>>>(xn, Wv_w, Wv_b, vb, M, CCH, CCH, nullptr, 0);

    // 3) LePE: depthwise 5x5 + GELU on V
    dwconv_kernel<<<(HW * CCH) / 256, 256>>>(vb, lepe_w, lepe_b, vlb, CCH, 0);

    // 4) sparse windowed attention (+vl), result in global pixel layout
    attn_kernel<<<dim3(NHEAD, NWIN), 256, ATTN_SMEM_BYTES>>>(
        qb, kb, vb, vlb, pfa_v, pfa_i, rpi, rpb_tab, attnb);

    // 5) output projection + shortcut (shortcut = transposed features)
    sgemm_kernel<0, 2><<<g192, 128>>>(attnb, proj_w, proj_b, x2b, M, CCH, CCH,
                                      features, HW);

    // 6) ConvFFN
    ln2_kernel<<<HW / 256, 256>>>(x2b, ln2_g, ln2_b, ylnb);
    dim3 g768(HIDN / 64, M / 128);
    sgemm_kernel<1, 0><<<g768, 128>>>(ylnb, fc1_w, fc1_b, ybb, M, HIDN, CCH,
                                      nullptr, 0);
    dwconv_kernel<<<(HW * HIDN) / 256, 256>>>(ybb, ffn_dw_w, ffn_dw_b, y2b, HIDN, 1);
    sgemm_kernel<0, 1><<<g192, 128>>>(y2b, fc2_w, fc2_b, outp, M, CCH, HIDN,
                                      x2b, 0);
    (void)in_sizes; (void)n_in; (void)out_size;
}

// round 2
// speedup vs baseline: 1.0282x; 1.0282x over previous
#include <cuda_runtime.h>
#include <cuda_bf16.h>
#include <math.h>

#define HW     36864
#define IMG    192
#define CCH    192
#define HIDN   768
#define NWIN   144
#define NHEAD  6
#define NTOK   256
#define KINN   128
#define TOPKN  64

// ---------------- scratch buffers (static, no allocation) ----------------
__device__ __align__(128) float g_xn  [HW*CCH];
__device__ __align__(128) float g_sct [HW*CCH];
__device__ __align__(128) float g_q   [HW*CCH];
__device__ __align__(128) float g_k   [HW*CCH];
__device__ __align__(128) float g_v   [HW*CCH];
__device__ __align__(128) float g_vl  [HW*CCH];
__device__ __align__(128) float g_attn[HW*CCH];
__device__ __align__(128) float g_x2  [HW*CCH];
__device__ __align__(128) float g_yln [HW*CCH];
__device__ __align__(128) float g_yb  [HW*HIDN];
__device__ __align__(128) float g_y2  [HW*HIDN];

__device__ __forceinline__ float gelu_f(float x) {
    return 0.5f * x * (1.0f + erff(x * 0.70710678118654752f));
}

// ---------------- LN1: transpose (C,HW)->(HW,C) + LayerNorm + raw transpose ---
#define LNP 48
__global__ void ln1_kernel(const float* __restrict__ f, const float* __restrict__ g,
                           const float* __restrict__ b, float* __restrict__ xn,
                           float* __restrict__ sct) {
    __shared__ float tile[LNP][193];
    __shared__ float mArr[LNP], rArr[LNP];
    const int t = threadIdx.x;
    const int p0 = blockIdx.x * LNP;
    for (int lin = t; lin < LNP * CCH; lin += 256) {
        int c = lin / LNP, p = lin % LNP;
        tile[p][c] = f[(size_t)c * HW + p0 + p];
    }
    __syncthreads();
    {
        int tq = t & 3, p = t >> 2;
        if (p < LNP) {
            float s = 0.f, s2 = 0.f;
            #pragma unroll 8
            for (int cc = 0; cc < 48; cc++) {
                float v = tile[p][tq * 48 + cc];
                s += v; s2 += v * v;
            }
            s  += __shfl_xor_sync(0xffffffffu, s, 1);
            s2 += __shfl_xor_sync(0xffffffffu, s2, 1);
            s  += __shfl_xor_sync(0xffffffffu, s, 2);
            s2 += __shfl_xor_sync(0xffffffffu, s2, 2);
            if (tq == 0) {
                float m = s * (1.f / CCH);
                float var = s2 * (1.f / CCH) - m * m;
                mArr[p] = m; rArr[p] = rsqrtf(var + 1e-5f);
            }
        }
    }
    __syncthreads();
    for (int lin = t; lin < LNP * CCH; lin += 256) {
        int p = lin / CCH, c = lin % CCH;
        float v = tile[p][c];
        size_t o = (size_t)(p0 + p) * CCH + c;
        sct[o] = v;
        xn[o] = (v - mArr[p]) * rArr[p] * g[c] + b[c];
    }
}

// ---------------- LN2: row-major (HW,C) LayerNorm, float4 ----------------
__global__ void ln2_kernel(const float* __restrict__ x, const float* __restrict__ g,
                           const float* __restrict__ b, float* __restrict__ y) {
    int p = blockIdx.x * 256 + threadIdx.x;
    const float4* row = (const float4*)(x + (size_t)p * CCH);
    float s = 0.f, s2 = 0.f;
    #pragma unroll
    for (int c = 0; c < CCH / 4; c++) {
        float4 v = row[c];
        s += v.x + v.y + v.z + v.w;
        s2 += v.x * v.x + v.y * v.y + v.z * v.z + v.w * v.w;
    }
    float m = s * (1.f / CCH);
    float var = s2 * (1.f / CCH) - m * m;
    float r = rsqrtf(var + 1e-5f);
    const float4* g4 = (const float4*)g;
    const float4* b4 = (const float4*)b;
    float4* orow = (float4*)(y + (size_t)p * CCH);
    #pragma unroll
    for (int c = 0; c < CCH / 4; c++) {
        float4 v = row[c], gg = g4[c], bb = b4[c], o;
        o.x = (v.x - m) * r * gg.x + bb.x;
        o.y = (v.y - m) * r * gg.y + bb.y;
        o.z = (v.z - m) * r * gg.z + bb.z;
        o.w = (v.w - m) * r * gg.w + bb.w;
        orow[c] = o;
    }
}

// ---------------- SGEMM: BM=128, BN=192, BK=16, 256 thr, double-buffered ------
// ACT: 0 none, 1 gelu. RES: 0 none, 1 += res[m*N+n]
template<int ACT, int RES>
__launch_bounds__(256)
__global__ void sgemm_kernel(const float* __restrict__ A, const float* __restrict__ B,
                             const float* __restrict__ bias, float* __restrict__ C,
                             int M, int N, int K, const float* __restrict__ res) {
    __shared__ float As[2][16][132];
    __shared__ float Bs[2][16][196];
    const int tid = threadIdx.x;
    const int m0 = blockIdx.y * 128, n0 = blockIdx.x * 192;
    const int txx = tid & 15, tyy = tid >> 4;

    // A-load mapping: 512 float4 over 256 threads (2 each)
    const int am = tid >> 2;             // row 0..63 (and +64)
    const int ak = (tid & 3) * 4;        // k 0,4,8,12
    // B-load mapping: 768 float4 over 256 threads (3 each)
    const int l0 = tid, l1 = tid + 256, l2 = tid + 512;
    const int bk0 = l0 / 48, bn0 = (l0 % 48) * 4;
    const int bk1 = l1 / 48, bn1 = (l1 % 48) * 4;
    const int bk2 = l2 / 48, bn2 = (l2 % 48) * 4;

    const float* Ag  = A + (size_t)(m0 + am) * K + ak;
    const float* Ag2 = Ag + (size_t)64 * K;
    const float* Bg0 = B + (size_t)bk0 * N + n0 + bn0;
    const float* Bg1 = B + (size_t)bk1 * N + n0 + bn1;
    const float* Bg2 = B + (size_t)bk2 * N + n0 + bn2;

    float acc[8][12];
    #pragma unroll
    for (int i = 0; i < 8; i++)
        #pragma unroll
        for (int j = 0; j < 12; j++) acc[i][j] = 0.f;

    // prologue: tile 0
    float4 ra0 = *(const float4*)Ag;
    float4 ra1 = *(const float4*)Ag2;
    float4 rb0 = *(const float4*)Bg0;
    float4 rb1 = *(const float4*)Bg1;
    float4 rb2 = *(const float4*)Bg2;
    As[0][ak + 0][am] = ra0.x; As[0][ak + 1][am] = ra0.y;
    As[0][ak + 2][am] = ra0.z; As[0][ak + 3][am] = ra0.w;
    As[0][ak + 0][64 + am] = ra1.x; As[0][ak + 1][64 + am] = ra1.y;
    As[0][ak + 2][64 + am] = ra1.z; As[0][ak + 3][64 + am] = ra1.w;
    *(float4*)&Bs[0][bk0][bn0] = rb0;
    *(float4*)&Bs[0][bk1][bn1] = rb1;
    *(float4*)&Bs[0][bk2][bn2] = rb2;
    __syncthreads();

    const int nT = K >> 4;
    int cur = 0;
    for (int t = 0; t < nT; t++) {
        if (t + 1 < nT) {
            size_t ko = (size_t)(t + 1) * 16;
            ra0 = *(const float4*)(Ag + ko);
            ra1 = *(const float4*)(Ag2 + ko);
            size_t bo = ko * N;
            rb0 = *(const float4*)(Bg0 + bo);
            rb1 = *(const float4*)(Bg1 + bo);
            rb2 = *(const float4*)(Bg2 + bo);
        }
        #pragma unroll
        for (int kk = 0; kk < 16; kk++) {
            float4 A0 = *(const float4*)&As[cur][kk][tyy * 4];
            float4 A1 = *(const float4*)&As[cur][kk][64 + tyy * 4];
            float4 B0 = *(const float4*)&Bs[cur][kk][txx * 4];
            float4 B1 = *(const float4*)&Bs[cur][kk][64 + txx * 4];
            float4 B2 = *(const float4*)&Bs[cur][kk][128 + txx * 4];
            float a[8] = {A0.x, A0.y, A0.z, A0.w, A1.x, A1.y, A1.z, A1.w};
            float bb[12] = {B0.x, B0.y, B0.z, B0.w, B1.x, B1.y, B1.z, B1.w,
                            B2.x, B2.y, B2.z, B2.w};
            #pragma unroll
            for (int i = 0; i < 8; i++)
                #pragma unroll
                for (int j = 0; j < 12; j++) acc[i][j] += a[i] * bb[j];
        }
        if (t + 1 < nT) {
            int nx = cur ^ 1;
            As[nx][ak + 0][am] = ra0.x; As[nx][ak + 1][am] = ra0.y;
            As[nx][ak + 2][am] = ra0.z; As[nx][ak + 3][am] = ra0.w;
            As[nx][ak + 0][64 + am] = ra1.x; As[nx][ak + 1][64 + am] = ra1.y;
            As[nx][ak + 2][64 + am] = ra1.z; As[nx][ak + 3][64 + am] = ra1.w;
            *(float4*)&Bs[nx][bk0][bn0] = rb0;
            *(float4*)&Bs[nx][bk1][bn1] = rb1;
            *(float4*)&Bs[nx][bk2][bn2] = rb2;
        }
        __syncthreads();
        cur ^= 1;
    }

    // epilogue
    #pragma unroll
    for (int i = 0; i < 8; i++) {
        int m = m0 + tyy * 4 + (i & 3) + (i >> 2) * 64;
        #pragma unroll
        for (int jc = 0; jc < 3; jc++) {
            int n = n0 + jc * 64 + txx * 4;
            float4 o;
            o.x = acc[i][jc * 4 + 0] + bias[n + 0];
            o.y = acc[i][jc * 4 + 1] + bias[n + 1];
            o.z = acc[i][jc * 4 + 2] + bias[n + 2];
            o.w = acc[i][jc * 4 + 3] + bias[n + 3];
            if (ACT == 1) {
                o.x = gelu_f(o.x); o.y = gelu_f(o.y);
                o.z = gelu_f(o.z); o.w = gelu_f(o.w);
            }
            if (RES == 1) {
                float4 rv = *(const float4*)(res + (size_t)m * N + n);
                o.x += rv.x; o.y += rv.y; o.z += rv.z; o.w += rv.w;
            }
            *(float4*)(C + (size_t)m * N + n) = o;
        }
    }
}

// ---------------- depthwise 5x5 conv (+bias) + exact GELU, opt input add ------
__global__ void dwconv_kernel(const float* __restrict__ in, const float* __restrict__ wgt,
                              const float* __restrict__ bias, float* __restrict__ out,
                              int Cn, int addin) {
    int idx = blockIdx.x * 256 + threadIdx.x;
    int nc4 = Cn >> 2;
    int c4 = idx % nc4, p = idx / nc4;
    int ch = c4 * 4;
    int y = p / IMG, x = p % IMG;
    float4 a = *(const float4*)(bias + ch);
    #pragma unroll
    for (int ky = 0; ky < 5; ky++) {
        int yy = y + ky - 2;
        if ((unsigned)yy >= (unsigned)IMG) continue;
        #pragma unroll
        for (int kx = 0; kx < 5; kx++) {
            int xx = x + kx - 2;
            if ((unsigned)xx >= (unsigned)IMG) continue;
            float4 v = *(const float4*)(in + (size_t)(yy * IMG + xx) * Cn + ch);
            int wb = ky * 5 + kx;
            a.x += v.x * wgt[(ch + 0) * 25 + wb];
            a.y += v.y * wgt[(ch + 1) * 25 + wb];
            a.z += v.z * wgt[(ch + 2) * 25 + wb];
            a.w += v.w * wgt[(ch + 3) * 25 + wb];
        }
    }
    float4 o;
    o.x = gelu_f(a.x); o.y = gelu_f(a.y); o.z = gelu_f(a.z); o.w = gelu_f(a.w);
    if (addin) {
        float4 iv = *(const float4*)(in + (size_t)p * Cn + ch);
        o.x += iv.x; o.y += iv.y; o.z += iv.z; o.w += iv.w;
    }
    *(float4*)(out + (size_t)p * Cn + ch) = o;
}

// ---------------- attention: one CTA per (head, window), 256 threads ----------
// smem: kv[256*36] (K, reused for V) + sc[128*256] + js(u8)[128*260] = 201216 B
#define ATTN_SMEM_BYTES (256*36*4 + 128*256*4 + 128*260)
__global__ void attn_kernel(const float* __restrict__ q, const float* __restrict__ k,
                            const float* __restrict__ v, const float* __restrict__ vl,
                            const float* __restrict__ pfa_v, const int* __restrict__ pfa_i,
                            const int* __restrict__ rpi, const float* __restrict__ rpb,
                            float* __restrict__ out) {
    extern __shared__ float sm[];
    float* kv = sm;                                     // 256*36
    float* sc = kv + 256 * 36;                          // [kk][256]
    unsigned char* js = (unsigned char*)(sc + 128 * 256);  // [kk][260]

    const int t = threadIdx.x;
    const int h = blockIdx.x;
    const int w = blockIdx.y;
    const int wy = w / 12, wx = w % 12;
    const size_t whbase = ((size_t)w * NHEAD + h) * NTOK;

    // stage K cooperatively: warp loads 4 rows x 8 float4
    #pragma unroll
    for (int rb = 0; rb < 256; rb += 32) {
        int r = rb + (t >> 3), e = t & 7;
        int pj = (wy * 16 + (r >> 4)) * IMG + wx * 16 + (r & 15);
        *(float4*)&kv[r * 36 + e * 4] =
            *(const float4*)(k + (size_t)pj * CCH + h * 32 + e * 4);
    }
    // stage gather indices (coalesced read, transposed u8 layout)
    {
        const int* idxg = pfa_i + whbase * KINN;
        for (int e = t; e < NTOK * KINN; e += 256)
            js[(e & 127) * 260 + (e >> 7)] = (unsigned char)idxg[e];
    }
    __syncthreads();

    const int i = t;
    const int pi = (wy * 16 + (i >> 4)) * IMG + wx * 16 + (i & 15);

    float qreg[32];
    {
        const float4* qr = (const float4*)(q + (size_t)pi * CCH + h * 32);
        const float scl = 0.17677669529663688f;  // 1/sqrt(32)
        #pragma unroll
        for (int e = 0; e < 8; e++) {
            float4 a4 = qr[e];
            qreg[e * 4 + 0] = a4.x * scl; qreg[e * 4 + 1] = a4.y * scl;
            qreg[e * 4 + 2] = a4.z * scl; qreg[e * 4 + 3] = a4.w * scl;
        }
    }

    // gathered scores + rpb
    const int* rr = rpi + i * NTOK;
    float mx = -1e30f;
    #pragma unroll 4
    for (int kk = 0; kk < KINN; kk++) {
        int j = js[kk * 260 + t];
        const float* kj = kv + j * 36;
        float d = 0.f;
        #pragma unroll
        for (int e = 0; e < 8; e++) {
            float4 k4 = *(const float4*)(kj + e * 4);
            d += qreg[e * 4 + 0] * k4.x + qreg[e * 4 + 1] * k4.y
               + qreg[e * 4 + 2] * k4.z + qreg[e * 4 + 3] * k4.w;
        }
        d += __ldg(&rpb[__ldg(&rr[j]) * NHEAD + h]);
        sc[kk * 256 + t] = d;
        mx = fmaxf(mx, d);
    }

    float sE = 0.f;
    #pragma unroll 4
    for (int kk = 0; kk < KINN; kk++) {
        float e = __expf(sc[kk * 256 + t] - mx);
        sc[kk * 256 + t] = e;
        sE += e;
    }

    // multiply by prior, build per-group maxima (16 groups of 8) in registers
    const float* pv = pfa_v + (whbase + i) * KINN;
    const float inv = 1.0f / sE;
    float sA = 0.f;
    float gmax[16];
    #pragma unroll
    for (int g = 0; g < 16; g++) {
        float gm = -3.f;
        #pragma unroll
        for (int e2 = 0; e2 < 8; e2 += 4) {
            int kk = g * 8 + e2;
            float4 p4 = *(const float4*)(pv + kk);
            float a0 = sc[(kk + 0) * 256 + t] * p4.x * inv;
            float a1 = sc[(kk + 1) * 256 + t] * p4.y * inv;
            float a2 = sc[(kk + 2) * 256 + t] * p4.z * inv;
            float a3 = sc[(kk + 3) * 256 + t] * p4.w * inv;
            sc[(kk + 0) * 256 + t] = a0; sc[(kk + 1) * 256 + t] = a1;
            sc[(kk + 2) * 256 + t] = a2; sc[(kk + 3) * 256 + t] = a3;
            sA += a0 + a1 + a2 + a3;
            gm = fmaxf(gm, fmaxf(fmaxf(a0, a1), fmaxf(a2, a3)));
        }
        gmax[g] = gm;
    }
    const float r2 = 1.0f / (sA + 1e-10f);

    // restage V over the K buffer
    __syncthreads();
    #pragma unroll
    for (int rb = 0; rb < 256; rb += 32) {
        int r = rb + (t >> 3), e = t & 7;
        int pj = (wy * 16 + (r >> 4)) * IMG + wx * 16 + (r & 15);
        *(float4*)&kv[r * 36 + e * 4] =
            *(const float4*)(v + (size_t)pj * CCH + h * 32 + e * 4);
    }
    __syncthreads();

    // top-64 grouped argmax (first-index-wins ties) fused with sparse AV
    float acc[32];
    #pragma unroll
    for (int dd = 0; dd < 32; dd++) acc[dd] = 0.f;
    for (int sel = 0; sel < TOPKN; sel++) {
        float best = gmax[0]; int bg = 0;
        #pragma unroll
        for (int g = 1; g < 16; g++)
            if (gmax[g] > best) { best = gmax[g]; bg = g; }
        // rescan group bg: argmax (first idx) + second max
        float m1 = -3.f, m2 = -3.f; int be = 0;
        #pragma unroll
        for (int e2 = 0; e2 < 8; e2++) {
            float vv = sc[(bg * 8 + e2) * 256 + t];
            if (vv > m1) { m2 = m1; m1 = vv; be = e2; }
            else m2 = fmaxf(m2, vv);
        }
        int bkk = bg * 8 + be;
        sc[bkk * 256 + t] = -3.f;
        #pragma unroll
        for (int g = 0; g < 16; g++) if (g == bg) gmax[g] = m2;

        int j = js[bkk * 260 + t];
        float wv = (m1 + 1e-10f) * r2;
        const float* vj = kv + j * 36;
        #pragma unroll
        for (int e = 0; e < 8; e++) {
            float4 v4 = *(const float4*)(vj + e * 4);
            acc[e * 4 + 0] += wv * v4.x; acc[e * 4 + 1] += wv * v4.y;
            acc[e * 4 + 2] += wv * v4.z; acc[e * 4 + 3] += wv * v4.w;
        }
    }

    // out = attn_out + v_LePE at global pixel (implicit window reverse)
    float* op = out + (size_t)pi * CCH + h * 32;
    const float* vp = vl + (size_t)pi * CCH + h * 32;
    #pragma unroll
    for (int e = 0; e < 8; e++) {
        float4 o;
        o.x = acc[e * 4 + 0] + vp[e * 4 + 0];
        o.y = acc[e * 4 + 1] + vp[e * 4 + 1];
        o.z = acc[e * 4 + 2] + vp[e * 4 + 2];
        o.w = acc[e * 4 + 3] + vp[e * 4 + 3];
        *(float4*)(op + e * 4) = o;
    }
}

// ---------------- launch ----------------
extern "C" void kernel_launch(void* const* d_in, const int* in_sizes, int n_in,
                              void* d_out, int out_size) {
    const float* features = (const float*)d_in[0];
    const float* pfa_v    = (const float*)d_in[1];
    const int*   pfa_i    = (const int*)  d_in[2];
    const int*   rpi      = (const int*)  d_in[3];
    const float* ln1_g    = (const float*)d_in[4];
    const float* ln1_b    = (const float*)d_in[5];
    const float* Wq_w     = (const float*)d_in[6];
    const float* Wq_b     = (const float*)d_in[7];
    const float* Wk_w     = (const float*)d_in[8];
    const float* Wk_b     = (const float*)d_in[9];
    const float* Wv_w     = (const float*)d_in[10];
    const float* Wv_b     = (const float*)d_in[11];
    const float* lepe_w   = (const float*)d_in[12];
    const float* lepe_b   = (const float*)d_in[13];
    const float* rpb_tab  = (const float*)d_in[14];
    const float* proj_w   = (const float*)d_in[15];
    const float* proj_b   = (const float*)d_in[16];
    const float* ln2_g    = (const float*)d_in[17];
    const float* ln2_b    = (const float*)d_in[18];
    const float* fc1_w    = (const float*)d_in[19];
    const float* fc1_b    = (const float*)d_in[20];
    const float* ffn_dw_w = (const float*)d_in[21];
    const float* ffn_dw_b = (const float*)d_in[22];
    const float* fc2_w    = (const float*)d_in[23];
    const float* fc2_b    = (const float*)d_in[24];
    float* outp = (float*)d_out;

    float *xn, *sct, *qb, *kb, *vb, *vlb, *attnb, *x2b, *ylnb, *ybb, *y2b;
    cudaGetSymbolAddress((void**)&xn,    g_xn);
    cudaGetSymbolAddress((void**)&sct,   g_sct);
    cudaGetSymbolAddress((void**)&qb,    g_q);
    cudaGetSymbolAddress((void**)&kb,    g_k);
    cudaGetSymbolAddress((void**)&vb,    g_v);
    cudaGetSymbolAddress((void**)&vlb,   g_vl);
    cudaGetSymbolAddress((void**)&attnb, g_attn);
    cudaGetSymbolAddress((void**)&x2b,   g_x2);
    cudaGetSymbolAddress((void**)&ylnb,  g_yln);
    cudaGetSymbolAddress((void**)&ybb,   g_yb);
    cudaGetSymbolAddress((void**)&y2b,   g_y2);

    cudaFuncSetAttribute(attn_kernel, cudaFuncAttributeMaxDynamicSharedMemorySize,
                         ATTN_SMEM_BYTES);

    const int M = HW;

    // 1) transpose + LN1 (+ raw transposed shortcut)
    ln1_kernel<<<HW / LNP, 256>>>(features, ln1_g, ln1_b, xn, sct);

    // 2) QKV projections
    dim3 g192(1, M / 128);
    sgemm_kernel<0, 0><<<g192, 256>>>(xn, Wq_w, Wq_b, qb, M, CCH, CCH, nullptr);
    sgemm_kernel<0, 0><<<g192, 256>>>(xn, Wk_w, Wk_b, kb, M, CCH, CCH, nullptr);
    sgemm_kernel<0, 0><<<g192, 256>>>(xn, Wv_w, Wv_b, vb, M, CCH, CCH, nullptr);

    // 3) LePE: depthwise 5x5 + GELU on V
    dwconv_kernel<<<(HW * (CCH / 4)) / 256, 256>>>(vb, lepe_w, lepe_b, vlb, CCH, 0);

    // 4) sparse windowed attention (+vl)
    attn_kernel<<<dim3(NHEAD, NWIN), 256, ATTN_SMEM_BYTES>>>(
        qb, kb, vb, vlb, pfa_v, pfa_i, rpi, rpb_tab, attnb);

    // 5) output projection + shortcut (coalesced transposed residual)
    sgemm_kernel<0, 1><<<g192, 256>>>(attnb, proj_w, proj_b, x2b, M, CCH, CCH, sct);

    // 6) ConvFFN
    ln2_kernel<<<HW / 256, 256>>>(x2b, ln2_g, ln2_b, ylnb);
    dim3 g768(HIDN / 192, M / 128);
    sgemm_kernel<1, 0><<<g768, 256>>>(ylnb, fc1_w, fc1_b, ybb, M, HIDN, CCH, nullptr);
    dwconv_kernel<<<(HW * (HIDN / 4)) / 256, 256>>>(ybb, ffn_dw_w, ffn_dw_b, y2b, HIDN, 1);
    sgemm_kernel<0, 1><<<g192, 256>>>(y2b, fc2_w, fc2_b, outp, M, CCH, HIDN, x2b);
    (void)in_sizes; (void)n_in; (void)out_size;
}

// round 9
// speedup vs baseline: 1.4412x; 1.4017x over previous
#include <cuda_runtime.h>
#include <cuda_bf16.h>
#include <math.h>

#define HW     36864
#define IMG    192
#define CCH    192
#define HIDN   768
#define NWIN   144
#define NHEAD  6
#define NTOK   256
#define KINN   128
#define TOPKN  64

// ---------------- scratch buffers (static, no allocation) ----------------
__device__ __align__(128) float g_xn  [HW*CCH];
__device__ __align__(128) float g_sct [HW*CCH];
__device__ __align__(128) float g_q   [HW*CCH];
__device__ __align__(128) float g_k   [HW*CCH];
__device__ __align__(128) float g_v   [HW*CCH];
__device__ __align__(128) float g_vl  [HW*CCH];
__device__ __align__(128) float g_attn[HW*CCH];
__device__ __align__(128) float g_x2  [HW*CCH];
__device__ __align__(128) float g_yln [HW*CCH];
__device__ __align__(128) float g_yb  [HW*HIDN];
__device__ __align__(128) float g_y2  [HW*HIDN];

__device__ __forceinline__ float gelu_f(float x) {
    return 0.5f * x * (1.0f + erff(x * 0.70710678118654752f));
}

__device__ __forceinline__ unsigned smem_u32(const void* p) {
    return (unsigned)__cvta_generic_to_shared(p);
}
__device__ __forceinline__ void cp16(unsigned dst, const void* src) {
    asm volatile("cp.async.cg.shared.global [%0], [%1], 16;\n" :: "r"(dst), "l"(src));
}
__device__ __forceinline__ void cp_commit() {
    asm volatile("cp.async.commit_group;\n");
}
template<int N>
__device__ __forceinline__ void cp_wait() {
    asm volatile("cp.async.wait_group %0;\n" :: "n"(N));
}

// ---------------- LN1: transpose (C,HW)->(HW,C) + LayerNorm + raw transpose ---
#define LNP 48
__global__ void ln1_kernel(const float* __restrict__ f, const float* __restrict__ g,
                           const float* __restrict__ b, float* __restrict__ xn,
                           float* __restrict__ sct) {
    __shared__ float tile[LNP][193];
    __shared__ float mArr[LNP], rArr[LNP];
    const int t = threadIdx.x;
    const int p0 = blockIdx.x * LNP;
    for (int lin = t; lin < LNP * CCH; lin += 256) {
        int c = lin / LNP, p = lin % LNP;
        tile[p][c] = f[(size_t)c * HW + p0 + p];
    }
    __syncthreads();
    {
        int tq = t & 3, p = t >> 2;
        if (p < LNP) {
            float s = 0.f, s2 = 0.f;
            #pragma unroll 8
            for (int cc = 0; cc < 48; cc++) {
                float v = tile[p][tq * 48 + cc];
                s += v; s2 += v * v;
            }
            s  += __shfl_xor_sync(0xffffffffu, s, 1);
            s2 += __shfl_xor_sync(0xffffffffu, s2, 1);
            s  += __shfl_xor_sync(0xffffffffu, s, 2);
            s2 += __shfl_xor_sync(0xffffffffu, s2, 2);
            if (tq == 0) {
                float m = s * (1.f / CCH);
                float var = s2 * (1.f / CCH) - m * m;
                mArr[p] = m; rArr[p] = rsqrtf(var + 1e-5f);
            }
        }
    }
    __syncthreads();
    for (int lin = t; lin < LNP * CCH; lin += 256) {
        int p = lin / CCH, c = lin % CCH;
        float v = tile[p][c];
        size_t o = (size_t)(p0 + p) * CCH + c;
        sct[o] = v;
        xn[o] = (v - mArr[p]) * rArr[p] * g[c] + b[c];
    }
}

// ---------------- LN2: row-major (HW,C) LayerNorm, float4 ----------------
__global__ void ln2_kernel(const float* __restrict__ x, const float* __restrict__ g,
                           const float* __restrict__ b, float* __restrict__ y) {
    int p = blockIdx.x * 256 + threadIdx.x;
    const float4* row = (const float4*)(x + (size_t)p * CCH);
    float s = 0.f, s2 = 0.f;
    #pragma unroll
    for (int c = 0; c < CCH / 4; c++) {
        float4 v = row[c];
        s += v.x + v.y + v.z + v.w;
        s2 += v.x * v.x + v.y * v.y + v.z * v.z + v.w * v.w;
    }
    float m = s * (1.f / CCH);
    float var = s2 * (1.f / CCH) - m * m;
    float r = rsqrtf(var + 1e-5f);
    const float4* g4 = (const float4*)g;
    const float4* b4 = (const float4*)b;
    float4* orow = (float4*)(y + (size_t)p * CCH);
    #pragma unroll
    for (int c = 0; c < CCH / 4; c++) {
        float4 v = row[c], gg = g4[c], bb = b4[c], o;
        o.x = (v.x - m) * r * gg.x + bb.x;
        o.y = (v.y - m) * r * gg.y + bb.y;
        o.z = (v.z - m) * r * gg.z + bb.z;
        o.w = (v.w - m) * r * gg.w + bb.w;
        orow[c] = o;
    }
}

// ---------------- SGEMM v3: BM=64, BN=192, BK=16, 128 thr, cp.async 3-stage ---
// ACT: 0 none, 1 gelu. RES: 0 none, 1 += res[m*N+n]
#define AS_STRIDE 20
#define BS_STRIDE 196
#define A_STAGE (64 * AS_STRIDE)        // 1280 floats
#define B_STAGE (16 * BS_STRIDE)        // 3136 floats
#define GEMM_SMEM_FLOATS (3 * A_STAGE + 3 * B_STAGE)
#define GEMM_SMEM_BYTES  (GEMM_SMEM_FLOATS * 4)

template<int ACT, int RES>
__global__ void __launch_bounds__(128, 3)
sgemm_kernel(const float* __restrict__ A, const float* __restrict__ B,
             const float* __restrict__ bias, float* __restrict__ C,
             int M, int N, int K, const float* __restrict__ res) {
    extern __shared__ float sm[];
    const int tid = threadIdx.x;
    const int m0 = blockIdx.y * 64, n0 = blockIdx.x * 192;
    const int txx = tid & 15, tyy = tid >> 4;

    // A chunk mapping: 2 chunks (rows am0, am0+32; k-offset ak0)
    const int am0 = tid >> 2, ak0 = (tid & 3) * 4;
    const float* Asrc = A + (size_t)(m0 + am0) * K + ak0;
    // B chunk mapping: 6 chunks
    int bk[6], bn[6];
    #pragma unroll
    for (int j = 0; j < 6; j++) {
        int lin = tid + j * 128;
        bk[j] = lin / 48; bn[j] = (lin % 48) * 4;
    }

    const int nT = K >> 4;

    // per-stage issue
    auto issue = [&](int slot, int kt) {
        if (kt < nT) {
            float* as = sm + slot * A_STAGE;
            float* bs = sm + 3 * A_STAGE + slot * B_STAGE;
            unsigned da0 = smem_u32(as + am0 * AS_STRIDE + ak0);
            unsigned da1 = smem_u32(as + (am0 + 32) * AS_STRIDE + ak0);
            cp16(da0, Asrc + (size_t)kt * 16);
            cp16(da1, Asrc + (size_t)32 * K + (size_t)kt * 16);
            #pragma unroll
            for (int j = 0; j < 6; j++) {
                unsigned db = smem_u32(bs + bk[j] * BS_STRIDE + bn[j]);
                cp16(db, B + (size_t)(kt * 16 + bk[j]) * N + n0 + bn[j]);
            }
        }
        cp_commit();
    };

    float acc[8][12];
    #pragma unroll
    for (int i = 0; i < 8; i++)
        #pragma unroll
        for (int j = 0; j < 12; j++) acc[i][j] = 0.f;

    issue(0, 0);
    issue(1, 1);

    for (int t = 0; t < nT; t++) {
        cp_wait<1>();
        __syncthreads();
        const int slot = t % 3;
        const float* as = sm + slot * A_STAGE;
        const float* bs = sm + 3 * A_STAGE + slot * B_STAGE;
        #pragma unroll 4
        for (int kk = 0; kk < 16; kk++) {
            float a[8], bb[12];
            #pragma unroll
            for (int i = 0; i < 8; i++)
                a[i] = as[(tyy + 8 * i) * AS_STRIDE + kk];
            #pragma unroll
            for (int j = 0; j < 3; j++) {
                float4 b4 = *(const float4*)&bs[kk * BS_STRIDE + j * 64 + txx * 4];
                bb[j * 4 + 0] = b4.x; bb[j * 4 + 1] = b4.y;
                bb[j * 4 + 2] = b4.z; bb[j * 4 + 3] = b4.w;
            }
            #pragma unroll
            for (int i = 0; i < 8; i++)
                #pragma unroll
                for (int j = 0; j < 12; j++) acc[i][j] += a[i] * bb[j];
        }
        issue((t + 2) % 3, t + 2);
    }

    // epilogue
    #pragma unroll
    for (int i = 0; i < 8; i++) {
        int m = m0 + tyy + 8 * i;
        #pragma unroll
        for (int jc = 0; jc < 3; jc++) {
            int n = n0 + jc * 64 + txx * 4;
            float4 o;
            o.x = acc[i][jc * 4 + 0] + bias[n + 0];
            o.y = acc[i][jc * 4 + 1] + bias[n + 1];
            o.z = acc[i][jc * 4 + 2] + bias[n + 2];
            o.w = acc[i][jc * 4 + 3] + bias[n + 3];
            if (ACT == 1) {
                o.x = gelu_f(o.x); o.y = gelu_f(o.y);
                o.z = gelu_f(o.z); o.w = gelu_f(o.w);
            }
            if (RES == 1) {
                float4 rv = *(const float4*)(res + (size_t)m * N + n);
                o.x += rv.x; o.y += rv.y; o.z += rv.z; o.w += rv.w;
            }
            *(float4*)(C + (size_t)m * N + n) = o;
        }
    }
}

// ---------------- dwconv v2: smem tile 8x8 px x 16 ch, 12x12 halo -------------
// block 256: c4l = tid&3, px = (tid>>2)&7, py = tid>>5
// grid: (576 tiles, Cn/16)
__global__ void dwconv_kernel(const float* __restrict__ in, const float* __restrict__ wgt,
                              const float* __restrict__ bias, float* __restrict__ out,
                              int Cn, int addin) {
    __shared__ float4 tile[12 * 12 * 4];
    __shared__ float wsm[16][26];
    const int tid = threadIdx.x;
    const int c4l = tid & 3, px = (tid >> 2) & 7, py = tid >> 5;
    const int c4b = blockIdx.y;
    const int gx0 = (blockIdx.x % 24) * 8, gy0 = (blockIdx.x / 24) * 8;

    // 400 weights staged by 256 threads -> strided loop (R4 fix)
    for (int lw = tid; lw < 400; lw += 256)
        wsm[lw / 25][lw % 25] = wgt[(c4b * 16 + lw / 25) * 25 + lw % 25];

    for (int lin = tid; lin < 576; lin += 256) {
        int cc = lin & 3, rem = lin >> 2;
        int xx = rem % 12, yy = rem / 12;
        int gy = gy0 + yy - 2, gx = gx0 + xx - 2;
        float4 v = make_float4(0.f, 0.f, 0.f, 0.f);
        if ((unsigned)gy < (unsigned)IMG && (unsigned)gx < (unsigned)IMG)
            v = *(const float4*)(in + (size_t)(gy * IMG + gx) * Cn + (c4b * 4 + cc) * 4);
        tile[(yy * 12 + xx) * 4 + cc] = v;
    }
    __syncthreads();

    float4 a = *(const float4*)(bias + (c4b * 4 + c4l) * 4);
    #pragma unroll
    for (int ky = 0; ky < 5; ky++) {
        #pragma unroll
        for (int kx = 0; kx < 5; kx++) {
            float4 v = tile[((py + ky) * 12 + px + kx) * 4 + c4l];
            int tp = ky * 5 + kx;
            a.x += v.x * wsm[c4l * 4 + 0][tp];
            a.y += v.y * wsm[c4l * 4 + 1][tp];
            a.z += v.z * wsm[c4l * 4 + 2][tp];
            a.w += v.w * wsm[c4l * 4 + 3][tp];
        }
    }
    float4 o;
    o.x = gelu_f(a.x); o.y = gelu_f(a.y); o.z = gelu_f(a.z); o.w = gelu_f(a.w);
    if (addin) {
        float4 iv = tile[((py + 2) * 12 + px + 2) * 4 + c4l];
        o.x += iv.x; o.y += iv.y; o.z += iv.z; o.w += iv.w;
    }
    *(float4*)(out + (size_t)((gy0 + py) * IMG + gx0 + px) * Cn + (c4b * 4 + c4l) * 4) = o;
}

// ---------------- attention: one CTA per (head, window), 256 threads ----------
// smem: kv[256*36] (K, reused for V) + sc[128*256] + js(u8)[128*260] = 201216 B
#define ATTN_SMEM_BYTES (256*36*4 + 128*256*4 + 128*260)
__global__ void attn_kernel(const float* __restrict__ q, const float* __restrict__ k,
                            const float* __restrict__ v, const float* __restrict__ vl,
                            const float* __restrict__ pfa_v, const int* __restrict__ pfa_i,
                            const int* __restrict__ rpi, const float* __restrict__ rpb,
                            float* __restrict__ out) {
    extern __shared__ float smA[];
    float* kv = smA;                                     // 256*36
    float* sc = kv + 256 * 36;                           // [kk][256]
    unsigned char* js = (unsigned char*)(sc + 128 * 256);  // [kk][260]

    const int t = threadIdx.x;
    const int h = blockIdx.x;
    const int w = blockIdx.y;
    const int wy = w / 12, wx = w % 12;
    const size_t whbase = ((size_t)w * NHEAD + h) * NTOK;

    #pragma unroll
    for (int rb = 0; rb < 256; rb += 32) {
        int r = rb + (t >> 3), e = t & 7;
        int pj = (wy * 16 + (r >> 4)) * IMG + wx * 16 + (r & 15);
        *(float4*)&kv[r * 36 + e * 4] =
            *(const float4*)(k + (size_t)pj * CCH + h * 32 + e * 4);
    }
    {
        const int* idxg = pfa_i + whbase * KINN;
        for (int e = t; e < NTOK * KINN; e += 256)
            js[(e & 127) * 260 + (e >> 7)] = (unsigned char)idxg[e];
    }
    __syncthreads();

    const int i = t;
    const int pi = (wy * 16 + (i >> 4)) * IMG + wx * 16 + (i & 15);

    float qreg[32];
    {
        const float4* qr = (const float4*)(q + (size_t)pi * CCH + h * 32);
        const float scl = 0.17677669529663688f;  // 1/sqrt(32)
        #pragma unroll
        for (int e = 0; e < 8; e++) {
            float4 a4 = qr[e];
            qreg[e * 4 + 0] = a4.x * scl; qreg[e * 4 + 1] = a4.y * scl;
            qreg[e * 4 + 2] = a4.z * scl; qreg[e * 4 + 3] = a4.w * scl;
        }
    }

    const int* rr = rpi + i * NTOK;
    float mx = -1e30f;
    #pragma unroll 4
    for (int kk = 0; kk < KINN; kk++) {
        int j = js[kk * 260 + t];
        const float* kj = kv + j * 36;
        float d = 0.f;
        #pragma unroll
        for (int e = 0; e < 8; e++) {
            float4 k4 = *(const float4*)(kj + e * 4);
            d += qreg[e * 4 + 0] * k4.x + qreg[e * 4 + 1] * k4.y
               + qreg[e * 4 + 2] * k4.z + qreg[e * 4 + 3] * k4.w;
        }
        d += __ldg(&rpb[__ldg(&rr[j]) * NHEAD + h]);
        sc[kk * 256 + t] = d;
        mx = fmaxf(mx, d);
    }

    float sE = 0.f;
    #pragma unroll 4
    for (int kk = 0; kk < KINN; kk++) {
        float e = __expf(sc[kk * 256 + t] - mx);
        sc[kk * 256 + t] = e;
        sE += e;
    }

    const float* pv = pfa_v + (whbase + i) * KINN;
    const float inv = 1.0f / sE;
    float sA = 0.f;
    float gmax[16];
    #pragma unroll
    for (int g = 0; g < 16; g++) {
        float gm = -3.f;
        #pragma unroll
        for (int e2 = 0; e2 < 8; e2 += 4) {
            int kk = g * 8 + e2;
            float4 p4 = *(const float4*)(pv + kk);
            float a0 = sc[(kk + 0) * 256 + t] * p4.x * inv;
            float a1 = sc[(kk + 1) * 256 + t] * p4.y * inv;
            float a2 = sc[(kk + 2) * 256 + t] * p4.z * inv;
            float a3 = sc[(kk + 3) * 256 + t] * p4.w * inv;
            sc[(kk + 0) * 256 + t] = a0; sc[(kk + 1) * 256 + t] = a1;
            sc[(kk + 2) * 256 + t] = a2; sc[(kk + 3) * 256 + t] = a3;
            sA += a0 + a1 + a2 + a3;
            gm = fmaxf(gm, fmaxf(fmaxf(a0, a1), fmaxf(a2, a3)));
        }
        gmax[g] = gm;
    }
    const float r2 = 1.0f / (sA + 1e-10f);

    __syncthreads();
    #pragma unroll
    for (int rb = 0; rb < 256; rb += 32) {
        int r = rb + (t >> 3), e = t & 7;
        int pj = (wy * 16 + (r >> 4)) * IMG + wx * 16 + (r & 15);
        *(float4*)&kv[r * 36 + e * 4] =
            *(const float4*)(v + (size_t)pj * CCH + h * 32 + e * 4);
    }
    __syncthreads();

    float acc[32];
    #pragma unroll
    for (int dd = 0; dd < 32; dd++) acc[dd] = 0.f;
    for (int sel = 0; sel < TOPKN; sel++) {
        float best = gmax[0]; int bg = 0;
        #pragma unroll
        for (int g = 1; g < 16; g++)
            if (gmax[g] > best) { best = gmax[g]; bg = g; }
        float m1 = -3.f, m2 = -3.f; int be = 0;
        #pragma unroll
        for (int e2 = 0; e2 < 8; e2++) {
            float vv = sc[(bg * 8 + e2) * 256 + t];
            if (vv > m1) { m2 = m1; m1 = vv; be = e2; }
            else m2 = fmaxf(m2, vv);
        }
        int bkk = bg * 8 + be;
        sc[bkk * 256 + t] = -3.f;
        #pragma unroll
        for (int g = 0; g < 16; g++) if (g == bg) gmax[g] = m2;

        int j = js[bkk * 260 + t];
        float wv = (m1 + 1e-10f) * r2;
        const float* vj = kv + j * 36;
        #pragma unroll
        for (int e = 0; e < 8; e++) {
            float4 v4 = *(const float4*)(vj + e * 4);
            acc[e * 4 + 0] += wv * v4.x; acc[e * 4 + 1] += wv * v4.y;
            acc[e * 4 + 2] += wv * v4.z; acc[e * 4 + 3] += wv * v4.w;
        }
    }

    float* op = out + (size_t)pi * CCH + h * 32;
    const float* vp = vl + (size_t)pi * CCH + h * 32;
    #pragma unroll
    for (int e = 0; e < 8; e++) {
        float4 o;
        o.x = acc[e * 4 + 0] + vp[e * 4 + 0];
        o.y = acc[e * 4 + 1] + vp[e * 4 + 1];
        o.z = acc[e * 4 + 2] + vp[e * 4 + 2];
        o.w = acc[e * 4 + 3] + vp[e * 4 + 3];
        *(float4*)(op + e * 4) = o;
    }
}

// ---------------- launch ----------------
extern "C" void kernel_launch(void* const* d_in, const int* in_sizes, int n_in,
                              void* d_out, int out_size) {
    const float* features = (const float*)d_in[0];
    const float* pfa_v    = (const float*)d_in[1];
    const int*   pfa_i    = (const int*)  d_in[2];
    const int*   rpi      = (const int*)  d_in[3];
    const float* ln1_g    = (const float*)d_in[4];
    const float* ln1_b    = (const float*)d_in[5];
    const float* Wq_w     = (const float*)d_in[6];
    const float* Wq_b     = (const float*)d_in[7];
    const float* Wk_w     = (const float*)d_in[8];
    const float* Wk_b     = (const float*)d_in[9];
    const float* Wv_w     = (const float*)d_in[10];
    const float* Wv_b     = (const float*)d_in[11];
    const float* lepe_w   = (const float*)d_in[12];
    const float* lepe_b   = (const float*)d_in[13];
    const float* rpb_tab  = (const float*)d_in[14];
    const float* proj_w   = (const float*)d_in[15];
    const float* proj_b   = (const float*)d_in[16];
    const float* ln2_g    = (const float*)d_in[17];
    const float* ln2_b    = (const float*)d_in[18];
    const float* fc1_w    = (const float*)d_in[19];
    const float* fc1_b    = (const float*)d_in[20];
    const float* ffn_dw_w = (const float*)d_in[21];
    const float* ffn_dw_b = (const float*)d_in[22];
    const float* fc2_w    = (const float*)d_in[23];
    const float* fc2_b    = (const float*)d_in[24];
    float* outp = (float*)d_out;

    float *xn, *sct, *qb, *kb, *vb, *vlb, *attnb, *x2b, *ylnb, *ybb, *y2b;
    cudaGetSymbolAddress((void**)&xn,    g_xn);
    cudaGetSymbolAddress((void**)&sct,   g_sct);
    cudaGetSymbolAddress((void**)&qb,    g_q);
    cudaGetSymbolAddress((void**)&kb,    g_k);
    cudaGetSymbolAddress((void**)&vb,    g_v);
    cudaGetSymbolAddress((void**)&vlb,   g_vl);
    cudaGetSymbolAddress((void**)&attnb, g_attn);
    cudaGetSymbolAddress((void**)&x2b,   g_x2);
    cudaGetSymbolAddress((void**)&ylnb,  g_yln);
    cudaGetSymbolAddress((void**)&ybb,   g_yb);
    cudaGetSymbolAddress((void**)&y2b,   g_y2);

    cudaFuncSetAttribute(attn_kernel, cudaFuncAttributeMaxDynamicSharedMemorySize,
                         ATTN_SMEM_BYTES);
    cudaFuncSetAttribute(sgemm_kernel<0, 0>, cudaFuncAttributeMaxDynamicSharedMemorySize,
                         GEMM_SMEM_BYTES);
    cudaFuncSetAttribute(sgemm_kernel<0, 1>, cudaFuncAttributeMaxDynamicSharedMemorySize,
                         GEMM_SMEM_BYTES);
    cudaFuncSetAttribute(sgemm_kernel<1, 0>, cudaFuncAttributeMaxDynamicSharedMemorySize,
                         GEMM_SMEM_BYTES);

    const int M = HW;

    // 1) transpose + LN1 (+ raw transposed shortcut)
    ln1_kernel<<<HW / LNP, 256>>>(features, ln1_g, ln1_b, xn, sct);

    // 2) QKV projections
    dim3 g192(1, M / 64);
    sgemm_kernel<0, 0><<<g192, 128, GEMM_SMEM_BYTES>>>(xn, Wq_w, Wq_b, qb, M, CCH, CCH, nullptr);
    sgemm_kernel<0, 0><<<g192, 128, GEMM_SMEM_BYTES>>>(xn, Wk_w, Wk_b, kb, M, CCH, CCH, nullptr);
    sgemm_kernel<0, 0><<<g192, 128, GEMM_SMEM_BYTES>>>(xn, Wv_w, Wv_b, vb, M, CCH, CCH, nullptr);

    // 3) LePE: depthwise 5x5 + GELU on V
    dwconv_kernel<<<dim3(576, CCH / 16), 256>>>(vb, lepe_w, lepe_b, vlb, CCH, 0);

    // 4) sparse windowed attention (+vl)
    attn_kernel<<<dim3(NHEAD, NWIN), 256, ATTN_SMEM_BYTES>>>(
        qb, kb, vb, vlb, pfa_v, pfa_i, rpi, rpb_tab, attnb);

    // 5) output projection + shortcut (coalesced transposed residual)
    sgemm_kernel<0, 1><<<g192, 128, GEMM_SMEM_BYTES>>>(attnb, proj_w, proj_b, x2b, M, CCH, CCH, sct);

    // 6) ConvFFN
    ln2_kernel<<<HW / 256, 256>>>(x2b, ln2_g, ln2_b, ylnb);
    dim3 g768(HIDN / 192, M / 64);
    sgemm_kernel<1, 0><<<g768, 128, GEMM_SMEM_BYTES>>>(ylnb, fc1_w, fc1_b, ybb, M, HIDN, CCH, nullptr);
    dwconv_kernel<<<dim3(576, HIDN / 16), 256>>>(ybb, ffn_dw_w, ffn_dw_b, y2b, HIDN, 1);
    sgemm_kernel<0, 1><<<g192, 128, GEMM_SMEM_BYTES>>>(y2b, fc2_w, fc2_b, outp, M, CCH, HIDN, x2b);
    (void)in_sizes; (void)n_in; (void)out_size;
}